// round 7
// baseline (speedup 1.0000x reference)
#include <cuda_runtime.h>

// Problem constants
#define B_    4
#define N_    512
#define T_    10
#define F_    516      // N + 4
#define HID   128
#define MSGD  32
#define UPDH  128
#define OUTD  4

// kB tiling
#define ITILE   4                   // i's per CTA
#define JSPLIT  4                   // j split across CTAs (blockIdx.z)
#define JCHUNK  (N_ / JSPLIT)       // 128 j per CTA
#define NWARP   4                   // warps per CTA (private j-groups)
#define JW      (JCHUNK / NWARP)    // 32 j per warp
#define KJ      2                   // j per staging round
#define RNDS    (JW / KJ)           // 16 rounds
#define NSLICE  (JSPLIT * NWARP)    // 16 partial slices

// Scratch (static device arrays: no allocations allowed)
__device__ float g_C[B_ * N_ * HID];                 // C[b,j,hid], mb1 folded in
__device__ float g_part[NSLICE * B_ * N_ * HID];     // per-warp partial H_sum

// ---------------------------------------------------------------------------
// packed fp32x2 helpers (sm_100+)
// ---------------------------------------------------------------------------
__device__ __forceinline__ float2 ffma2(float2 a, float2 b, float2 c) {
    float2 d;
    asm("fma.rn.f32x2 %0, %1, %2, %3;"
        : "=l"(reinterpret_cast<unsigned long long&>(d))
        : "l"(reinterpret_cast<unsigned long long&>(a)),
          "l"(reinterpret_cast<unsigned long long&>(b)),
          "l"(reinterpret_cast<unsigned long long&>(c)));
    return d;
}
__device__ __forceinline__ float2 fadd2(float2 a, float2 b) {
    float2 d;
    asm("add.rn.f32x2 %0, %1, %2;"
        : "=l"(reinterpret_cast<unsigned long long&>(d))
        : "l"(reinterpret_cast<unsigned long long&>(a)),
          "l"(reinterpret_cast<unsigned long long&>(b)));
    return d;
}

// ---------------------------------------------------------------------------
// Kernel A: C[b,j,hid] = mb1[hid] + sum_{t,k<4} x[b,j,t,k] * mW1[5t+k, hid]
// 1024 blocks x 128 threads; weights in 40 regs; 2 (b,j) per block.
// ---------------------------------------------------------------------------
#define ABJ 2
__global__ __launch_bounds__(128) void kA(const float* __restrict__ x,
                                          const float* __restrict__ mW1,
                                          const float* __restrict__ mb1) {
    const int hid = threadIdx.x;
    float w[40];
#pragma unroll
    for (int r = 0; r < 40; ++r)
        w[r] = mW1[(5 * (r >> 2) + (r & 3)) * HID + hid];
    const float bias = mb1[hid];

    __shared__ float sb[ABJ][40];
    const int bj0 = blockIdx.x * ABJ;
    if (hid < ABJ * 40) {
        const int nn = hid / 40, r = hid % 40;
        sb[nn][r] = x[((long)(bj0 + nn) * T_ + (r >> 2)) * F_ + (r & 3)];
    }
    __syncthreads();

    float acc[ABJ];
#pragma unroll
    for (int nn = 0; nn < ABJ; ++nn) acc[nn] = bias;
#pragma unroll
    for (int r = 0; r < 40; ++r) {
        const float wr = w[r];
#pragma unroll
        for (int nn = 0; nn < ABJ; ++nn) acc[nn] = fmaf(sb[nn][r], wr, acc[nn]);
    }
#pragma unroll
    for (int nn = 0; nn < ABJ; ++nn)
        g_C[(long)(bj0 + nn) * HID + hid] = acc[nn];
}

// ---------------------------------------------------------------------------
// Kernel B (dominant):
//   H_sum[b,i,:] = sum_j relu( C[b,j,:] + sum_t e[b,j,t,i] * w_t[:] )
// CTA = (itile of 4 i, b, j-quarter). 128 threads / 4 warps, each warp owning
// a private 32-j stream covering 4 i x 128 hid. Lane owns 4 hids; f32x2 acc
// packed over i; DUPLICATED weights live in SMEM (10 KB, conflict-free
// LDS.128), loaded once per t and shared across KJ=2 interleaved j's.
// Low register count (~95) -> 5 CTAs/SM (20 warps). No CTA barriers in loop.
// ---------------------------------------------------------------------------
__global__ __launch_bounds__(128, 5) void kB(const float* __restrict__ x,
                                             const float* __restrict__ mW1) {
    const int tid  = threadIdx.x;
    const int warp = tid >> 5, lane = tid & 31;
    const int itile = blockIdx.x;            // 0..127
    const int b     = blockIdx.y;            // 0..3
    const int js    = blockIdx.z;            // 0..3
    const int i0    = itile * ITILE;
    const int hid0  = lane * 4;              // 4 hids per lane

    // Duplicated weights in SMEM: s_w[t][2h] = s_w[t][2h+1] = w_t[h]
    __shared__ __align__(16) float  s_w[T_][2 * HID];              // 10 KB
    __shared__ __align__(16) float4 e_s[NWARP][2][KJ][T_];         // 2.5 KB

    for (int idx = tid; idx < T_ * HID; idx += 128) {
        const int t = idx >> 7, h = idx & 127;
        const float v = mW1[(5 * t + 4) * HID + h];
        s_w[t][2 * h]     = v;
        s_w[t][2 * h + 1] = v;
    }
    __syncthreads();

    const int  jbase = js * JCHUNK + warp * JW;
    const bool ldr   = (lane < KJ * T_);     // 20 loader lanes
    const int  ljj   = lane / T_;            // which j of the round (0/1)
    const int  lt    = lane % T_;            // t
    const long estr  = (long)T_ * F_;        // x stride per j

    const float* egp = x + ((long)(b * N_ + jbase + ljj) * T_ + lt) * F_ + 4 + i0;
    const float* cgp = g_C + (long)(b * N_ + jbase) * HID + hid0;

    float4 eH;             // loader-held e (one float4 per lane per round)
    float4 cC[KJ], cN[KJ]; // current / next c per lane

    // Prologue: stage round 0, preload round 1 into eH, c(round 0) into cC
    if (ldr) {
        eH = *reinterpret_cast<const float4*>(egp);
        e_s[warp][0][ljj][lt] = eH;
        eH = *reinterpret_cast<const float4*>(egp + (long)KJ * estr);
    }
#pragma unroll
    for (int jj = 0; jj < KJ; ++jj)
        cC[jj] = *reinterpret_cast<const float4*>(cgp + (long)jj * HID);
    __syncwarp();

    float2 acc[2][4];   // [i-pair][hid]
#pragma unroll
    for (int ip = 0; ip < 2; ++ip)
#pragma unroll
        for (int h = 0; h < 4; ++h) acc[ip][h] = make_float2(0.f, 0.f);

#pragma unroll 2
    for (int r = 0; r < RNDS; ++r) {
        const int cur = r & 1;

        // prefetch c for round r+1
        if (r + 1 < RNDS) {
            const long jb = (long)(r + 1) * KJ;
#pragma unroll
            for (int jj = 0; jj < KJ; ++jj)
                cN[jj] = *reinterpret_cast<const float4*>(cgp + (jb + jj) * HID);
        }

        // ---- compute round r: KJ j's interleaved over t (w loads shared) ----
        float2 p[KJ][2][4];   // [jj][i-pair][hid]
#pragma unroll
        for (int jj = 0; jj < KJ; ++jj) {
            p[jj][0][0] = make_float2(cC[jj].x, cC[jj].x);
            p[jj][0][1] = make_float2(cC[jj].y, cC[jj].y);
            p[jj][0][2] = make_float2(cC[jj].z, cC[jj].z);
            p[jj][0][3] = make_float2(cC[jj].w, cC[jj].w);
            p[jj][1][0] = p[jj][0][0];
            p[jj][1][1] = p[jj][0][1];
            p[jj][1][2] = p[jj][0][2];
            p[jj][1][3] = p[jj][0][3];
        }
#pragma unroll
        for (int t = 0; t < T_; ++t) {
            const float4 wA = *reinterpret_cast<const float4*>(&s_w[t][2 * hid0]);     // {w0,w0,w1,w1}
            const float4 wB = *reinterpret_cast<const float4*>(&s_w[t][2 * hid0 + 4]); // {w2,w2,w3,w3}
            const float2 w0 = make_float2(wA.x, wA.y);
            const float2 w1 = make_float2(wA.z, wA.w);
            const float2 w2 = make_float2(wB.x, wB.y);
            const float2 w3 = make_float2(wB.z, wB.w);
#pragma unroll
            for (int jj = 0; jj < KJ; ++jj) {
                const float4 e4 = e_s[warp][cur][jj][t];   // all 4 i's, one LDS.128
                const float2 ea = make_float2(e4.x, e4.y); // i-pair 0
                const float2 eb = make_float2(e4.z, e4.w); // i-pair 1
                p[jj][0][0] = ffma2(ea, w0, p[jj][0][0]);
                p[jj][0][1] = ffma2(ea, w1, p[jj][0][1]);
                p[jj][0][2] = ffma2(ea, w2, p[jj][0][2]);
                p[jj][0][3] = ffma2(ea, w3, p[jj][0][3]);
                p[jj][1][0] = ffma2(eb, w0, p[jj][1][0]);
                p[jj][1][1] = ffma2(eb, w1, p[jj][1][1]);
                p[jj][1][2] = ffma2(eb, w2, p[jj][1][2]);
                p[jj][1][3] = ffma2(eb, w3, p[jj][1][3]);
            }
        }
#pragma unroll
        for (int jj = 0; jj < KJ; ++jj)
#pragma unroll
            for (int ip = 0; ip < 2; ++ip)
#pragma unroll
                for (int h = 0; h < 4; ++h)
                    acc[ip][h] = fadd2(acc[ip][h],
                        make_float2(fmaxf(p[jj][ip][h].x, 0.f),
                                    fmaxf(p[jj][ip][h].y, 0.f)));

        // stage round r+1 (held in eH), then refill eH with round r+2; rotate c
        if (r + 1 < RNDS) {
            if (ldr) {
                e_s[warp][cur ^ 1][ljj][lt] = eH;
                if (r + 2 < RNDS)
                    eH = *reinterpret_cast<const float4*>(egp + (long)(r + 2) * KJ * estr);
            }
#pragma unroll
            for (int jj = 0; jj < KJ; ++jj) cC[jj] = cN[jj];
        }
        __syncwarp();
    }

    // ---- epilogue: warp writes its own partial slice (no CTA reduction) ----
    {
        const int slice = js * NWARP + warp;
        float* dst = g_part + ((long)slice * (B_ * N_) + (long)b * N_ + i0) * HID + hid0;
#pragma unroll
        for (int i = 0; i < ITILE; ++i) {
            const int ip = i >> 1;
            float4 v;
            if ((i & 1) == 0)
                v = make_float4(acc[ip][0].x, acc[ip][1].x, acc[ip][2].x, acc[ip][3].x);
            else
                v = make_float4(acc[ip][0].y, acc[ip][1].y, acc[ip][2].y, acc[ip][3].y);
            *reinterpret_cast<float4*>(dst + (long)i * HID) = v;
        }
    }
}

// ---------------------------------------------------------------------------
// Kernel C: per node — reduce 16 partial slices, apply mW2 (+ N*mb2),
// concat node_feat, 36 -> 128 (relu) -> 4 MLP. Block = 16 nodes, weights smem.
// ---------------------------------------------------------------------------
#define NPB 16
__global__ __launch_bounds__(128) void kC(const float* __restrict__ x,
                                          const float* __restrict__ mW2,
                                          const float* __restrict__ mb2,
                                          const float* __restrict__ iW1,
                                          const float* __restrict__ ib1,
                                          const float* __restrict__ iW2,
                                          const float* __restrict__ ib2,
                                          float* __restrict__ out) {
    const int tid = threadIdx.x;

    __shared__ float s_mW2[HID * MSGD];          // 16 KB
    __shared__ float s_iW1[(MSGD + 4) * UPDH];   // 18 KB
    __shared__ float s_iW2[UPDH * OUTD];         // 2 KB
    __shared__ float s_mb2[MSGD], s_ib1[UPDH], s_ib2[OUTD];
    __shared__ float s_h[HID];
    __shared__ float s_red[4][MSGD];
    __shared__ float s_mi[MSGD + 4];
    __shared__ float s_h2[UPDH];
    __shared__ float s_nf[NPB][4];

    for (int i = tid; i < HID * MSGD; i += 128)        s_mW2[i] = mW2[i];
    for (int i = tid; i < (MSGD + 4) * UPDH; i += 128) s_iW1[i] = iW1[i];
    for (int i = tid; i < UPDH * OUTD; i += 128)       s_iW2[i] = iW2[i];
    if (tid < MSGD) s_mb2[tid] = mb2[tid];
    s_ib1[tid] = ib1[tid];
    if (tid < OUTD) s_ib2[tid] = ib2[tid];
    if (tid < NPB * 4) {
        const int nn = tid >> 2, k = tid & 3;
        s_nf[nn][k] = x[((long)(blockIdx.x * NPB + nn) * T_ + (T_ - 1)) * F_ + k];
    }
    __syncthreads();

    for (int nn = 0; nn < NPB; ++nn) {
        const long node = (long)blockIdx.x * NPB + nn;

        float h = 0.f;
#pragma unroll
        for (int p = 0; p < NSLICE; ++p)
            h += g_part[(long)p * (B_ * N_ * HID) + node * HID + tid];
        s_h[tid] = h;
        __syncthreads();

        {   // mW2 GEMV split 4 ways over k
            const int m = tid & 31, seg = tid >> 5;
            float a = 0.f;
#pragma unroll
            for (int k2 = 0; k2 < 32; ++k2) {
                const int k = seg * 32 + k2;
                a = fmaf(s_h[k], s_mW2[k * MSGD + m], a);
            }
            s_red[seg][m] = a;
        }
        __syncthreads();
        if (tid < MSGD)
            s_mi[tid] = s_red[0][tid] + s_red[1][tid] + s_red[2][tid] + s_red[3][tid]
                      + (float)N_ * s_mb2[tid];
        if (tid < 4) s_mi[MSGD + tid] = s_nf[nn][tid];
        __syncthreads();

        {   // 36 -> 128 relu
            float a = s_ib1[tid];
#pragma unroll
            for (int k = 0; k < MSGD + 4; ++k)
                a = fmaf(s_mi[k], s_iW1[k * UPDH + tid], a);
            s_h2[tid] = fmaxf(a, 0.f);
        }
        __syncthreads();

        {   // 128 -> 4: warp o computes output o, shuffle-reduce
            const int o = tid >> 5, lane = tid & 31;
            float a = 0.f;
#pragma unroll
            for (int kk = 0; kk < 4; ++kk) {
                const int k = lane + kk * 32;
                a = fmaf(s_h2[k], s_iW2[k * OUTD + o], a);
            }
#pragma unroll
            for (int off = 16; off; off >>= 1) a += __shfl_xor_sync(~0u, a, off);
            if (lane == 0) out[node * OUTD + o] = a + s_ib2[o];
        }
        __syncthreads();
    }
}

// ---------------------------------------------------------------------------
extern "C" void kernel_launch(void* const* d_in, const int* in_sizes, int n_in,
                              void* d_out, int out_size) {
    const float* x   = (const float*)d_in[0];
    const float* mW1 = (const float*)d_in[1];
    const float* mb1 = (const float*)d_in[2];
    const float* mW2 = (const float*)d_in[3];
    const float* mb2 = (const float*)d_in[4];
    const float* iW1 = (const float*)d_in[5];
    const float* ib1 = (const float*)d_in[6];
    const float* iW2 = (const float*)d_in[7];
    const float* ib2 = (const float*)d_in[8];
    float* out = (float*)d_out;

    kA<<<B_ * N_ / ABJ, HID>>>(x, mW1, mb1);          // 1024 blocks

    dim3 gB(N_ / ITILE, B_, JSPLIT);                  // (128, 4, 4) = 2048 CTAs
    kB<<<gB, 128>>>(x, mW1);

    kC<<<B_ * N_ / NPB, HID>>>(x, mW2, mb2, iW1, ib1, iW2, ib2, out);
}

// round 8
// speedup vs baseline: 1.6054x; 1.6054x over previous
#include <cuda_runtime.h>

// Problem constants
#define B_    4
#define N_    512
#define T_    10
#define F_    516      // N + 4
#define HID   128
#define MSGD  32
#define UPDH  128
#define OUTD  4

// kB tiling
#define ITILE   4                   // i's per CTA
#define JSPLIT  4                   // j split across CTAs (blockIdx.z)
#define JCHUNK  (N_ / JSPLIT)       // 128 j per CTA
#define NWARP   4                   // warps per CTA (private j-groups)
#define JW      (JCHUNK / NWARP)    // 32 j per warp
#define KJ      2                   // j per staging round
#define RNDS    (JW / KJ)           // 16 rounds
#define NSLICE  (JSPLIT * NWARP)    // 16 partial slices

// Scratch (static device arrays: no allocations allowed)
__device__ float g_C[B_ * N_ * HID];                 // C[b,j,hid], mb1 folded in
__device__ float g_part[NSLICE * B_ * N_ * HID];     // per-warp partial H_sum

// ---------------------------------------------------------------------------
// packed fp32x2 helpers (sm_100+)
// ---------------------------------------------------------------------------
__device__ __forceinline__ float2 ffma2(float2 a, float2 b, float2 c) {
    float2 d;
    asm("fma.rn.f32x2 %0, %1, %2, %3;"
        : "=l"(reinterpret_cast<unsigned long long&>(d))
        : "l"(reinterpret_cast<unsigned long long&>(a)),
          "l"(reinterpret_cast<unsigned long long&>(b)),
          "l"(reinterpret_cast<unsigned long long&>(c)));
    return d;
}
__device__ __forceinline__ float2 fadd2(float2 a, float2 b) {
    float2 d;
    asm("add.rn.f32x2 %0, %1, %2;"
        : "=l"(reinterpret_cast<unsigned long long&>(d))
        : "l"(reinterpret_cast<unsigned long long&>(a)),
          "l"(reinterpret_cast<unsigned long long&>(b)));
    return d;
}

// ---------------------------------------------------------------------------
// Kernel A: C[b,j,hid] = mb1[hid] + sum_{t,k<4} x[b,j,t,k] * mW1[5t+k, hid]
// 1024 blocks x 128 threads; weights in 40 regs; 2 (b,j) per block.
// ---------------------------------------------------------------------------
#define ABJ 2
__global__ __launch_bounds__(128) void kA(const float* __restrict__ x,
                                          const float* __restrict__ mW1,
                                          const float* __restrict__ mb1) {
    const int hid = threadIdx.x;
    float w[40];
#pragma unroll
    for (int r = 0; r < 40; ++r)
        w[r] = mW1[(5 * (r >> 2) + (r & 3)) * HID + hid];
    const float bias = mb1[hid];

    __shared__ float sb[ABJ][40];
    const int bj0 = blockIdx.x * ABJ;
    if (hid < ABJ * 40) {
        const int nn = hid / 40, r = hid % 40;
        sb[nn][r] = x[((long)(bj0 + nn) * T_ + (r >> 2)) * F_ + (r & 3)];
    }
    __syncthreads();

    float acc[ABJ];
#pragma unroll
    for (int nn = 0; nn < ABJ; ++nn) acc[nn] = bias;
#pragma unroll
    for (int r = 0; r < 40; ++r) {
        const float wr = w[r];
#pragma unroll
        for (int nn = 0; nn < ABJ; ++nn) acc[nn] = fmaf(sb[nn][r], wr, acc[nn]);
    }
#pragma unroll
    for (int nn = 0; nn < ABJ; ++nn)
        g_C[(long)(bj0 + nn) * HID + hid] = acc[nn];
}

// ---------------------------------------------------------------------------
// Kernel B (dominant):
//   H_sum[b,i,:] = sum_j relu( C[b,j,:] + sum_t e[b,j,t,i] * w_t[:] )
// CTA = (itile of 4 i, b, j-quarter). 128 threads / 4 warps, each warp owning
// a private 32-j stream covering 4 i x 128 hid. Lane owns 4 hids; f32x2 acc
// packed over i; weights duplicated {w,w} in 80 REGISTERS (broadcast-free).
// e staged per-warp in smem as float4-over-i, read via BROADCAST LDS.128
// (N=1, all lanes same address). c pipelined at j-granularity in 8 regs.
// __launch_bounds__(128,4): cap 128 regs -> 4 CTAs/SM (16 warps).
// ---------------------------------------------------------------------------
__global__ __launch_bounds__(128, 4) void kB(const float* __restrict__ x,
                                             const float* __restrict__ mW1) {
    const int tid  = threadIdx.x;
    const int warp = tid >> 5, lane = tid & 31;
    const int itile = blockIdx.x;            // 0..127
    const int b     = blockIdx.y;            // 0..3
    const int js    = blockIdx.z;            // 0..3
    const int i0    = itile * ITILE;
    const int hid0  = lane * 4;              // 4 hids per lane

    // Duplicated weights {w,w}: 4 hid x 10 t (loop-invariant, 80 regs)
    float2 wd[T_][4];
#pragma unroll
    for (int t = 0; t < T_; ++t) {
        float4 wv = *reinterpret_cast<const float4*>(&mW1[(5 * t + 4) * HID + hid0]);
        wd[t][0] = make_float2(wv.x, wv.x);
        wd[t][1] = make_float2(wv.y, wv.y);
        wd[t][2] = make_float2(wv.z, wv.z);
        wd[t][3] = make_float2(wv.w, wv.w);
    }

    // Per-warp e staging: [warp][buf][jj][t] as float4 over i (2.5 KB total)
    __shared__ __align__(16) float4 e_s[NWARP][2][KJ][T_];

    const int  jbase = js * JCHUNK + warp * JW;
    const bool ldr   = (lane < KJ * T_);     // 20 loader lanes
    const int  ljj   = lane / T_;            // which j of the round (0/1)
    const int  lt    = lane % T_;            // t
    const long estr  = (long)T_ * F_;        // x stride per j

    const float* egp = x + ((long)(b * N_ + jbase + ljj) * T_ + lt) * F_ + 4 + i0;
    const float* cgp = g_C + (long)(b * N_ + jbase) * HID + hid0;

    float4 eH;       // loader-held e (one float4 per lane per round)

    // Prologue: stage round 0, preload round 1 into eH; c(j=0) into c_cur
    if (ldr) {
        eH = *reinterpret_cast<const float4*>(egp);
        e_s[warp][0][ljj][lt] = eH;
        eH = *reinterpret_cast<const float4*>(egp + (long)KJ * estr);
    }
    float4 c_cur = *reinterpret_cast<const float4*>(cgp);
    __syncwarp();

    float2 acc[2][4];   // [i-pair][hid]
#pragma unroll
    for (int ip = 0; ip < 2; ++ip)
#pragma unroll
        for (int h = 0; h < 4; ++h) acc[ip][h] = make_float2(0.f, 0.f);

#pragma unroll 2
    for (int r = 0; r < RNDS; ++r) {
        const int cur = r & 1;

#pragma unroll
        for (int jj = 0; jj < KJ; ++jj) {
            const int jglob = r * KJ + jj;

            // prefetch c for next j (distance-1 pipeline, 8 regs total)
            float4 c_nxt;
            if (jglob + 1 < JW)
                c_nxt = *reinterpret_cast<const float4*>(cgp + (long)(jglob + 1) * HID);

            // ---- compute edge block (4 i x 4 hid, f32x2 packed over i) ----
            float2 pA0 = make_float2(c_cur.x, c_cur.x);
            float2 pA1 = make_float2(c_cur.y, c_cur.y);
            float2 pA2 = make_float2(c_cur.z, c_cur.z);
            float2 pA3 = make_float2(c_cur.w, c_cur.w);
            float2 pB0 = pA0, pB1 = pA1, pB2 = pA2, pB3 = pA3;
#pragma unroll
            for (int t = 0; t < T_; ++t) {
                const float4 e4 = e_s[warp][cur][jj][t];   // broadcast LDS.128
                const float2 ea = make_float2(e4.x, e4.y); // i-pair 0
                const float2 eb = make_float2(e4.z, e4.w); // i-pair 1
                pA0 = ffma2(ea, wd[t][0], pA0);
                pA1 = ffma2(ea, wd[t][1], pA1);
                pA2 = ffma2(ea, wd[t][2], pA2);
                pA3 = ffma2(ea, wd[t][3], pA3);
                pB0 = ffma2(eb, wd[t][0], pB0);
                pB1 = ffma2(eb, wd[t][1], pB1);
                pB2 = ffma2(eb, wd[t][2], pB2);
                pB3 = ffma2(eb, wd[t][3], pB3);
            }
            acc[0][0] = fadd2(acc[0][0], make_float2(fmaxf(pA0.x, 0.f), fmaxf(pA0.y, 0.f)));
            acc[0][1] = fadd2(acc[0][1], make_float2(fmaxf(pA1.x, 0.f), fmaxf(pA1.y, 0.f)));
            acc[0][2] = fadd2(acc[0][2], make_float2(fmaxf(pA2.x, 0.f), fmaxf(pA2.y, 0.f)));
            acc[0][3] = fadd2(acc[0][3], make_float2(fmaxf(pA3.x, 0.f), fmaxf(pA3.y, 0.f)));
            acc[1][0] = fadd2(acc[1][0], make_float2(fmaxf(pB0.x, 0.f), fmaxf(pB0.y, 0.f)));
            acc[1][1] = fadd2(acc[1][1], make_float2(fmaxf(pB1.x, 0.f), fmaxf(pB1.y, 0.f)));
            acc[1][2] = fadd2(acc[1][2], make_float2(fmaxf(pB2.x, 0.f), fmaxf(pB2.y, 0.f)));
            acc[1][3] = fadd2(acc[1][3], make_float2(fmaxf(pB3.x, 0.f), fmaxf(pB3.y, 0.f)));

            c_cur = c_nxt;
        }

        // stage round r+1 (held in eH), then refill eH with round r+2
        if (r + 1 < RNDS) {
            if (ldr) {
                e_s[warp][cur ^ 1][ljj][lt] = eH;
                if (r + 2 < RNDS)
                    eH = *reinterpret_cast<const float4*>(egp + (long)(r + 2) * KJ * estr);
            }
        }
        __syncwarp();
    }

    // ---- epilogue: warp writes its own partial slice (no CTA reduction) ----
    {
        const int slice = js * NWARP + warp;
        float* dst = g_part + ((long)slice * (B_ * N_) + (long)b * N_ + i0) * HID + hid0;
#pragma unroll
        for (int i = 0; i < ITILE; ++i) {
            const int ip = i >> 1;
            float4 v;
            if ((i & 1) == 0)
                v = make_float4(acc[ip][0].x, acc[ip][1].x, acc[ip][2].x, acc[ip][3].x);
            else
                v = make_float4(acc[ip][0].y, acc[ip][1].y, acc[ip][2].y, acc[ip][3].y);
            *reinterpret_cast<float4*>(dst + (long)i * HID) = v;
        }
    }
}

// ---------------------------------------------------------------------------
// Kernel C: per node — reduce 16 partial slices, apply mW2 (+ N*mb2),
// concat node_feat, 36 -> 128 (relu) -> 4 MLP. Block = 16 nodes, weights smem.
// ---------------------------------------------------------------------------
#define NPB 16
__global__ __launch_bounds__(128) void kC(const float* __restrict__ x,
                                          const float* __restrict__ mW2,
                                          const float* __restrict__ mb2,
                                          const float* __restrict__ iW1,
                                          const float* __restrict__ ib1,
                                          const float* __restrict__ iW2,
                                          const float* __restrict__ ib2,
                                          float* __restrict__ out) {
    const int tid = threadIdx.x;

    __shared__ float s_mW2[HID * MSGD];          // 16 KB
    __shared__ float s_iW1[(MSGD + 4) * UPDH];   // 18 KB
    __shared__ float s_iW2[UPDH * OUTD];         // 2 KB
    __shared__ float s_mb2[MSGD], s_ib1[UPDH], s_ib2[OUTD];
    __shared__ float s_h[HID];
    __shared__ float s_red[4][MSGD];
    __shared__ float s_mi[MSGD + 4];
    __shared__ float s_h2[UPDH];
    __shared__ float s_nf[NPB][4];

    for (int i = tid; i < HID * MSGD; i += 128)        s_mW2[i] = mW2[i];
    for (int i = tid; i < (MSGD + 4) * UPDH; i += 128) s_iW1[i] = iW1[i];
    for (int i = tid; i < UPDH * OUTD; i += 128)       s_iW2[i] = iW2[i];
    if (tid < MSGD) s_mb2[tid] = mb2[tid];
    s_ib1[tid] = ib1[tid];
    if (tid < OUTD) s_ib2[tid] = ib2[tid];
    if (tid < NPB * 4) {
        const int nn = tid >> 2, k = tid & 3;
        s_nf[nn][k] = x[((long)(blockIdx.x * NPB + nn) * T_ + (T_ - 1)) * F_ + k];
    }
    __syncthreads();

    for (int nn = 0; nn < NPB; ++nn) {
        const long node = (long)blockIdx.x * NPB + nn;

        float h = 0.f;
#pragma unroll
        for (int p = 0; p < NSLICE; ++p)
            h += g_part[(long)p * (B_ * N_ * HID) + node * HID + tid];
        s_h[tid] = h;
        __syncthreads();

        {   // mW2 GEMV split 4 ways over k
            const int m = tid & 31, seg = tid >> 5;
            float a = 0.f;
#pragma unroll
            for (int k2 = 0; k2 < 32; ++k2) {
                const int k = seg * 32 + k2;
                a = fmaf(s_h[k], s_mW2[k * MSGD + m], a);
            }
            s_red[seg][m] = a;
        }
        __syncthreads();
        if (tid < MSGD)
            s_mi[tid] = s_red[0][tid] + s_red[1][tid] + s_red[2][tid] + s_red[3][tid]
                      + (float)N_ * s_mb2[tid];
        if (tid < 4) s_mi[MSGD + tid] = s_nf[nn][tid];
        __syncthreads();

        {   // 36 -> 128 relu
            float a = s_ib1[tid];
#pragma unroll
            for (int k = 0; k < MSGD + 4; ++k)
                a = fmaf(s_mi[k], s_iW1[k * UPDH + tid], a);
            s_h2[tid] = fmaxf(a, 0.f);
        }
        __syncthreads();

        {   // 128 -> 4: warp o computes output o, shuffle-reduce
            const int o = tid >> 5, lane = tid & 31;
            float a = 0.f;
#pragma unroll
            for (int kk = 0; kk < 4; ++kk) {
                const int k = lane + kk * 32;
                a = fmaf(s_h2[k], s_iW2[k * OUTD + o], a);
            }
#pragma unroll
            for (int off = 16; off; off >>= 1) a += __shfl_xor_sync(~0u, a, off);
            if (lane == 0) out[node * OUTD + o] = a + s_ib2[o];
        }
        __syncthreads();
    }
}

// ---------------------------------------------------------------------------
extern "C" void kernel_launch(void* const* d_in, const int* in_sizes, int n_in,
                              void* d_out, int out_size) {
    const float* x   = (const float*)d_in[0];
    const float* mW1 = (const float*)d_in[1];
    const float* mb1 = (const float*)d_in[2];
    const float* mW2 = (const float*)d_in[3];
    const float* mb2 = (const float*)d_in[4];
    const float* iW1 = (const float*)d_in[5];
    const float* ib1 = (const float*)d_in[6];
    const float* iW2 = (const float*)d_in[7];
    const float* ib2 = (const float*)d_in[8];
    float* out = (float*)d_out;

    kA<<<B_ * N_ / ABJ, HID>>>(x, mW1, mb1);          // 1024 blocks

    dim3 gB(N_ / ITILE, B_, JSPLIT);                  // (128, 4, 4) = 2048 CTAs
    kB<<<gB, 128>>>(x, mW1);

    kC<<<B_ * N_ / NPB, HID>>>(x, mW2, mb2, iW1, ib1, iW2, ib2, out);
}